// round 17
// baseline (speedup 1.0000x reference)
#include <cuda_runtime.h>
#include <cuda_bf16.h>
#include <cuda_fp16.h>
#include <cstdint>

#define B_  32
#define T_  256
#define C_  2048
#define H_  16
#define D_  128
#define M_TOT (B_*T_)     // 8192
#define BH_  (B_*H_)      // 512

// ------------------------------------------------------------------
// Device globals
// ------------------------------------------------------------------
__device__ float g_cos[T_*64];
__device__ float g_sin[T_*64];
__device__ __half g_x16[(size_t)M_TOT*C_];
__device__ __half g_w16[(size_t)4*C_*C_];
__device__ __half g_y16[(size_t)M_TOT*C_];
__device__ __half g_q16[(size_t)BH_*T_*D_];   // roped Q, pre-scaled 1/sqrt(D)
__device__ __half g_k16[(size_t)BH_*T_*D_];   // roped K
__device__ __half g_v16[(size_t)BH_*T_*D_];

// ------------------------------------------------------------------
// PTX helpers
// ------------------------------------------------------------------
__device__ __forceinline__ uint32_t smem_u32(const void* p) {
    uint32_t a;
    asm("{ .reg .u64 t; cvta.to.shared.u64 t, %1; cvt.u32.u64 %0, t; }" : "=r"(a) : "l"(p));
    return a;
}
__device__ __forceinline__ uint32_t h2u(__half2 h) {
    return *reinterpret_cast<uint32_t*>(&h);
}
__device__ __forceinline__ void cp16(uint32_t dst, const void* src) {
    asm volatile("cp.async.cg.shared.global [%0], [%1], 16;" :: "r"(dst), "l"(src));
}
__device__ __forceinline__ void cp_commit() {
    asm volatile("cp.async.commit_group;" ::: "memory");
}
__device__ __forceinline__ void ldmx4(uint32_t* r, uint32_t addr) {
    asm volatile("ldmatrix.sync.aligned.m8n8.x4.shared.b16 {%0,%1,%2,%3}, [%4];"
                 : "=r"(r[0]), "=r"(r[1]), "=r"(r[2]), "=r"(r[3]) : "r"(addr));
}
__device__ __forceinline__ void ldmx4t(uint32_t* r, uint32_t addr) {
    asm volatile("ldmatrix.sync.aligned.m8n8.x4.trans.shared.b16 {%0,%1,%2,%3}, [%4];"
                 : "=r"(r[0]), "=r"(r[1]), "=r"(r[2]), "=r"(r[3]) : "r"(addr));
}
__device__ __forceinline__ void mma16816h(float* d, const uint32_t* a, const uint32_t* b) {
    asm volatile(
        "mma.sync.aligned.m16n8k16.row.col.f32.f16.f16.f32 "
        "{%0,%1,%2,%3}, {%4,%5,%6,%7}, {%8,%9}, {%0,%1,%2,%3};"
        : "+f"(d[0]), "+f"(d[1]), "+f"(d[2]), "+f"(d[3])
        : "r"(a[0]), "r"(a[1]), "r"(a[2]), "r"(a[3]), "r"(b[0]), "r"(b[1]));
}
// Swizzle for [rows][32 x 16-bit] tiles (64B rows)
__device__ __forceinline__ uint32_t swz(int r, int c) {
    return (uint32_t)(r * 64 + ((c ^ ((r >> 1) & 3)) << 4));
}
// Swizzle for [rows][64 x 16-bit] tiles (128B rows)
__device__ __forceinline__ uint32_t swz128(int r, int c) {
    return (uint32_t)(r * 128 + ((c ^ (r & 7)) << 4));
}

#define SCALE 0.08838834764831845f

// ------------------------------------------------------------------
// Combined fp32 -> fp16 conversion for x and all 4 weights.
// ------------------------------------------------------------------
__global__ __launch_bounds__(256)
void split_all(const float4* __restrict__ x,
               const float4* __restrict__ w0, const float4* __restrict__ w1,
               const float4* __restrict__ w2, const float4* __restrict__ w3)
{
    const int seg = blockIdx.y;
    const float4* src;
    __half2* dp;
    if (seg < 4) {
        src = x + (size_t)seg * 1048576;
        dp  = (__half2*)g_x16 + (size_t)seg * 2097152;
    } else {
        const int s = seg - 4;
        src = (s == 0) ? w0 : (s == 1) ? w1 : (s == 2) ? w2 : w3;
        dp  = (__half2*)(g_w16 + (size_t)s * C_ * C_);
    }
    int i0 = blockIdx.x * 1024 + threadIdx.x;
    float4 v[4];
    #pragma unroll
    for (int k = 0; k < 4; k++) v[k] = src[i0 + k * 256];
    #pragma unroll
    for (int k = 0; k < 4; k++) {
        int i = i0 + k * 256;
        dp[2*i]   = __floats2half2_rn(v[k].x, v[k].y);
        dp[2*i+1] = __floats2half2_rn(v[k].z, v[k].w);
    }
}

// ------------------------------------------------------------------
// RoPE tables
// ------------------------------------------------------------------
__global__ void rope_table_kernel()
{
    int idx = blockIdx.x * blockDim.x + threadIdx.x;
    if (idx >= T_ * 64) return;
    int j = idx & 63;
    int t = idx >> 6;
    double inv = exp(-(double)j * (9.210340371976184 / 64.0));
    double th = (double)t * inv;
    g_cos[idx] = (float)cos(th);
    g_sin[idx] = (float)sin(th);
}

// ------------------------------------------------------------------
// fp16 HMMA GEMM (128 thr, 4 warps 64x64, 3 stages, 2 CTA/SM).
// mode 1: x @ w{q,k,v}^T. For Q/K the epilogue applies RoPE (fp32 acc,
//   staged through pipeline smem) and writes roped fp16 to g_q16/g_k16.
//   Q additionally scaled by 1/sqrt(D). V written fp16 directly.
// mode 0: y @ wo^T -> Out fp32 [M, C].
// ------------------------------------------------------------------
#define G16_STAGE 32768             // A 16KB | B 16KB
#define G16_SMEM (1024 + 3*G16_STAGE)

__global__ __launch_bounds__(128, 2)
void gemm16(float* __restrict__ Out, int mode)
{
    extern __shared__ char dsm[];
    const int tid  = threadIdx.x;
    const int wid  = tid >> 5;
    const int lane = tid & 31;
    const int bn = blockIdx.x * 128;
    const int bm = blockIdx.y * 128;
    const int wz = blockIdx.z;

    const __half* A_g = (mode == 0) ? g_y16 : g_x16;
    const int widx = (mode == 0) ? 3 : wz;
    const __half* B_g = g_w16 + (size_t)widx * C_ * C_;

    const uint32_t base = (smem_u32(dsm) + 1023u) & ~1023u;

    auto load_stage = [&](int kt, int s) {
        const uint32_t sb = base + (uint32_t)s * G16_STAGE;
        const int kb = kt * 64;
        #pragma unroll
        for (int it = 0; it < 8; it++) {
            int idx = tid + it * 128;
            int r = idx >> 3, c = idx & 7;
            uint32_t off = swz128(r, c);
            cp16(sb + off,         A_g + (size_t)(bm + r) * C_ + kb + c * 8);
            cp16(sb + 16384 + off, B_g + (size_t)(bn + r) * C_ + kb + c * 8);
        }
        cp_commit();
    };

    const int wm = (wid >> 1) * 64;
    const int wn = (wid & 1) * 64;
    const int arow = wm + (lane & 15);
    const int acol_base = (lane >> 4);
    const int brow = wn + (lane & 7) + ((lane & 16) >> 1);
    const int bcol_base = ((lane >> 3) & 1);

    float acc[4][8][4];
    #pragma unroll
    for (int i = 0; i < 4; i++)
        #pragma unroll
        for (int j = 0; j < 8; j++)
            #pragma unroll
            for (int q = 0; q < 4; q++) acc[i][j][q] = 0.0f;

    const int NK = C_ / 64;

    load_stage(0, 0);
    load_stage(1, 1);

    for (int c = 0; c < NK; c++) {
        __syncthreads();
        if (c + 2 < NK) load_stage(c + 2, (c + 2) % 3);
        else            cp_commit();
        asm volatile("cp.async.wait_group 2;" ::: "memory");
        __syncthreads();

        const uint32_t sA = base + (uint32_t)(c % 3) * G16_STAGE;
        const uint32_t sB = sA + 16384;

        #pragma unroll
        for (int ks = 0; ks < 4; ks++) {
            uint32_t ah[4][4];
            #pragma unroll
            for (int mt = 0; mt < 4; mt++)
                ldmx4(ah[mt], sA + swz128(arow + mt * 16, ks * 2 + acol_base));
            uint32_t bh[8][2];
            #pragma unroll
            for (int ng = 0; ng < 4; ng++) {
                uint32_t q[4];
                ldmx4(q, sB + swz128(brow + ng * 16, ks * 2 + bcol_base));
                bh[2*ng][0] = q[0]; bh[2*ng][1] = q[1];
                bh[2*ng+1][0] = q[2]; bh[2*ng+1][1] = q[3];
            }
            #pragma unroll
            for (int mt = 0; mt < 4; mt++)
                #pragma unroll
                for (int nt = 0; nt < 8; nt++)
                    mma16816h(acc[mt][nt], ah[mt], bh[nt]);
        }
    }

    if (mode == 1 && wz < 2) {
        // ---- RoPE epilogue for Q/K: stage fp32 tile, rotate, emit fp16 ----
        __syncthreads();                       // pipeline smem now free
        float* st = (float*)dsm;               // [128][132] fp32 = 67.6 KB
        #pragma unroll
        for (int mt = 0; mt < 4; mt++)
            #pragma unroll
            for (int nt = 0; nt < 8; nt++)
                #pragma unroll
                for (int half = 0; half < 2; half++) {
                    const int rl = wm + mt * 16 + (lane >> 2) + half * 8;
                    const int cl = wn + nt * 8 + (lane & 3) * 2;
                    st[rl * 132 + cl]     = acc[mt][nt][half * 2 + 0];
                    st[rl * 132 + cl + 1] = acc[mt][nt][half * 2 + 1];
                }
        __syncthreads();

        __half* dst = (wz == 0) ? g_q16 : g_k16;
        const int h = bn >> 7;
        const int grow = bm + tid;
        const int b = grow >> 8, t = grow & 255;
        __half* dp = dst + (((size_t)b * H_ + h) * T_ + t) * D_;
        const float* cs = g_cos + t * 64;
        const float* sn = g_sin + t * 64;
        const float sc = (wz == 0) ? SCALE : 1.0f;
        #pragma unroll
        for (int j = 0; j < 16; j++) {
            float4 xl = *(float4*)&st[tid * 132 + j * 4];
            float4 xh = *(float4*)&st[tid * 132 + 64 + j * 4];
            float4 c4 = *(const float4*)&cs[j * 4];
            float4 s4 = *(const float4*)&sn[j * 4];
            float a0 = (xl.x * c4.x - xh.x * s4.x) * sc;
            float a1 = (xl.y * c4.y - xh.y * s4.y) * sc;
            float a2 = (xl.z * c4.z - xh.z * s4.z) * sc;
            float a3 = (xl.w * c4.w - xh.w * s4.w) * sc;
            float b0 = (xh.x * c4.x + xl.x * s4.x) * sc;
            float b1 = (xh.y * c4.y + xl.y * s4.y) * sc;
            float b2 = (xh.z * c4.z + xl.z * s4.z) * sc;
            float b3 = (xh.w * c4.w + xl.w * s4.w) * sc;
            *(__half2*)(dp + j * 4)          = __floats2half2_rn(a0, a1);
            *(__half2*)(dp + j * 4 + 2)      = __floats2half2_rn(a2, a3);
            *(__half2*)(dp + 64 + j * 4)     = __floats2half2_rn(b0, b1);
            *(__half2*)(dp + 64 + j * 4 + 2) = __floats2half2_rn(b2, b3);
        }
    } else {
        #pragma unroll
        for (int mt = 0; mt < 4; mt++) {
            const int row0 = bm + wm + mt * 16 + (lane >> 2);
            #pragma unroll
            for (int nt = 0; nt < 8; nt++) {
                const int col = bn + wn + nt * 8 + (lane & 3) * 2;
                #pragma unroll
                for (int half = 0; half < 2; half++) {
                    const int row = row0 + half * 8;
                    float y0 = acc[mt][nt][half * 2 + 0];
                    float y1 = acc[mt][nt][half * 2 + 1];
                    if (mode == 0) {
                        float2 v; v.x = y0; v.y = y1;
                        *(float2*)(Out + (size_t)row * C_ + col) = v;
                    } else {
                        const int b = row >> 8, t = row & 255;
                        const int hh = col >> 7, d0 = col & 127;
                        const size_t ix = (((size_t)b * H_ + hh) * T_ + t) * D_ + d0;
                        *(__half2*)(g_v16 + ix) = __floats2half2_rn(y0, y1);
                    }
                }
            }
        }
    }
}

// ------------------------------------------------------------------
// Fused flash attention (pure cp.async loads; rope already applied).
// KT = number of 128-key tiles. One CTA per bh per q-block.
// smem: Q[4][128][32] 32KB | K[4][KT*128][32] | V[KT*128][272B]
// KT=1: 98KB -> 2 CTAs/SM; KT=2: 164KB -> 1 CTA/SM.
// ------------------------------------------------------------------
#define AF_SQ 0
#define AF_SK 32768
#define AF_SMEM(KT) (1024 + 32768 + (KT)*32768 + (KT)*34816)

template<int KT>
__global__ __launch_bounds__(256, 1)
void attn_fused()
{
    extern __shared__ char dsm[];
    const int tid  = threadIdx.x;
    const int w    = tid >> 5;
    const int lane = tid & 31;
    const int bh   = blockIdx.x;
    const int qt   = KT - 1;

    const __half* Qg = g_q16 + ((size_t)bh * T_ + qt * 128) * D_;
    const __half* Kg = g_k16 + (size_t)bh * T_ * D_;
    const __half* Vg = g_v16 + (size_t)bh * T_ * D_;

    const uint32_t base = (smem_u32(dsm) + 1023u) & ~1023u;
    const uint32_t sQ = base + AF_SQ;
    const uint32_t sK = base + AF_SK;
    const uint32_t sV = base + AF_SK + (uint32_t)KT * 32768;

    // ---- all loads via cp.async, one group ----
    #pragma unroll
    for (int it = 0; it < KT * 8; it++) {            // V
        int idx = tid + it * 256;
        int r = idx >> 4, dc = idx & 15;
        cp16(sV + (uint32_t)r * 272 + dc * 16, Vg + (size_t)r * D_ + dc * 8);
    }
    #pragma unroll
    for (int it = 0; it < KT * 8; it++) {            // K
        int idx = tid + it * 256;
        int r = idx >> 4, d16 = idx & 15;
        int c = d16 >> 2, ic = d16 & 3;
        cp16(sK + (uint32_t)c * (KT * 8192) + swz(r, ic), Kg + (size_t)r * D_ + d16 * 8);
    }
    #pragma unroll
    for (int it = 0; it < 8; it++) {                 // Q
        int idx = tid + it * 256;
        int r = idx >> 4, d16 = idx & 15;
        int c = d16 >> 2, ic = d16 & 3;
        cp16(sQ + (uint32_t)c * 8192 + swz(r, ic), Qg + (size_t)r * D_ + d16 * 8);
    }
    cp_commit();
    asm volatile("cp.async.wait_group 0;" ::: "memory");
    __syncthreads();

    // ---- S = Q K^T ----
    const int NT = KT * 16;
    const int arow = 16 * w + (lane & 15);
    const int acol_base = (lane >> 4);
    const int brow_l = (lane & 7) + ((lane & 16) >> 1);
    const int bcol_base = ((lane >> 3) & 1);

    float acc[NT][4];
    #pragma unroll
    for (int i = 0; i < NT; i++)
        #pragma unroll
        for (int q = 0; q < 4; q++) acc[i][q] = 0.0f;

    #pragma unroll
    for (int c4 = 0; c4 < 4; c4++) {
        #pragma unroll
        for (int ks = 0; ks < 2; ks++) {
            uint32_t qa[4];
            ldmx4(qa, sQ + (uint32_t)c4 * 8192 + swz(arow, ks * 2 + acol_base));
            #pragma unroll
            for (int g = 0; g < KT * 8; g++) {
                uint32_t bb[4];
                ldmx4(bb, sK + (uint32_t)c4 * (KT * 8192) + swz(g * 16 + brow_l, ks * 2 + bcol_base));
                mma16816h(acc[2*g],   qa, bb);
                mma16816h(acc[2*g+1], qa, bb + 2);
            }
        }
    }

    // ---- causal mask + softmax ----
    const int row_lo = qt * 128 + 16 * w + (lane >> 2);
    const int row_hi = row_lo + 8;
    const float NEG = -1e30f;
    #pragma unroll
    for (int nt = 0; nt < NT; nt++) {
        const int col0 = nt * 8 + (lane & 3) * 2;
        if (col0     > row_lo) acc[nt][0] = NEG;
        if (col0 + 1 > row_lo) acc[nt][1] = NEG;
        if (col0     > row_hi) acc[nt][2] = NEG;
        if (col0 + 1 > row_hi) acc[nt][3] = NEG;
    }
    float mlo = NEG, mhi = NEG;
    #pragma unroll
    for (int nt = 0; nt < NT; nt++) {
        mlo = fmaxf(mlo, fmaxf(acc[nt][0], acc[nt][1]));
        mhi = fmaxf(mhi, fmaxf(acc[nt][2], acc[nt][3]));
    }
    mlo = fmaxf(mlo, __shfl_xor_sync(0xffffffffu, mlo, 1));
    mlo = fmaxf(mlo, __shfl_xor_sync(0xffffffffu, mlo, 2));
    mhi = fmaxf(mhi, __shfl_xor_sync(0xffffffffu, mhi, 1));
    mhi = fmaxf(mhi, __shfl_xor_sync(0xffffffffu, mhi, 2));
    float slo = 0.f, shi = 0.f;
    #pragma unroll
    for (int nt = 0; nt < NT; nt++) {
        acc[nt][0] = __expf(acc[nt][0] - mlo);
        acc[nt][1] = __expf(acc[nt][1] - mlo);
        acc[nt][2] = __expf(acc[nt][2] - mhi);
        acc[nt][3] = __expf(acc[nt][3] - mhi);
        slo += acc[nt][0] + acc[nt][1];
        shi += acc[nt][2] + acc[nt][3];
    }
    slo += __shfl_xor_sync(0xffffffffu, slo, 1);
    slo += __shfl_xor_sync(0xffffffffu, slo, 2);
    shi += __shfl_xor_sync(0xffffffffu, shi, 1);
    shi += __shfl_xor_sync(0xffffffffu, shi, 2);
    const float ilo = 1.0f / slo;
    const float ihi = 1.0f / shi;

    uint32_t pf[KT * 8][4];
    #pragma unroll
    for (int j = 0; j < KT * 8; j++) {
        pf[j][0] = h2u(__floats2half2_rn(acc[2*j][0] * ilo, acc[2*j][1] * ilo));
        pf[j][1] = h2u(__floats2half2_rn(acc[2*j][2] * ihi, acc[2*j][3] * ihi));
        pf[j][2] = h2u(__floats2half2_rn(acc[2*j+1][0] * ilo, acc[2*j+1][1] * ilo));
        pf[j][3] = h2u(__floats2half2_rn(acc[2*j+1][2] * ihi, acc[2*j+1][3] * ihi));
    }

    // ---- O = P V ----
    const int kl_part = ((lane >> 3) & 1) * 8 + (lane & 7);
    const int nblk = lane >> 4;

    float oacc[16][4];
    #pragma unroll
    for (int i = 0; i < 16; i++)
        #pragma unroll
        for (int q = 0; q < 4; q++) oacc[i][q] = 0.0f;

    #pragma unroll
    for (int j = 0; j < KT * 8; j++) {
        #pragma unroll
        for (int dp = 0; dp < 8; dp++) {
            uint32_t bb[4];
            ldmx4t(bb, sV + (uint32_t)(j * 16 + kl_part) * 272 + (uint32_t)(dp * 2 + nblk) * 16);
            mma16816h(oacc[2*dp],   pf[j], bb);
            mma16816h(oacc[2*dp+1], pf[j], bb + 2);
        }
    }

    // ---- epilogue: y fp16 [B, T, C] ----
    const int b = bh >> 4, h = bh & 15;
    #pragma unroll
    for (int nt = 0; nt < 16; nt++) {
        const int d = nt * 8 + (lane & 3) * 2;
        const size_t ix_lo = ((size_t)b * T_ + row_lo) * C_ + h * D_ + d;
        const size_t ix_hi = ((size_t)b * T_ + row_hi) * C_ + h * D_ + d;
        *(__half2*)(g_y16 + ix_lo) = __floats2half2_rn(oacc[nt][0], oacc[nt][1]);
        *(__half2*)(g_y16 + ix_hi) = __floats2half2_rn(oacc[nt][2], oacc[nt][3]);
    }
}

// ------------------------------------------------------------------
extern "C" void kernel_launch(void* const* d_in, const int* in_sizes, int n_in,
                              void* d_out, int out_size)
{
    const float* x  = (const float*)d_in[0];
    const float* wq = (const float*)d_in[1];
    const float* wk = (const float*)d_in[2];
    const float* wv = (const float*)d_in[3];
    const float* wo = (const float*)d_in[4];
    float* out = (float*)d_out;

    cudaFuncSetAttribute(gemm16, cudaFuncAttributeMaxDynamicSharedMemorySize, G16_SMEM);
    cudaFuncSetAttribute(attn_fused<1>, cudaFuncAttributeMaxDynamicSharedMemorySize, AF_SMEM(1));
    cudaFuncSetAttribute(attn_fused<2>, cudaFuncAttributeMaxDynamicSharedMemorySize, AF_SMEM(2));

    // #1: all conversions
    split_all<<<dim3(1024, 8), 256>>>((const float4*)x, (const float4*)wq,
                                      (const float4*)wk, (const float4*)wv,
                                      (const float4*)wo);
    // #2: rope tables (needed by QKV GEMM epilogue)
    rope_table_kernel<<<(T_*64 + 255)/256, 256>>>();

    // #3: QKV projections with fused RoPE epilogue
    gemm16<<<dim3(C_/128, M_TOT/128, 3), 128, G16_SMEM>>>(nullptr, 1);

    // #4/#5: fused attention
    attn_fused<2><<<BH_, 256, AF_SMEM(2)>>>();
    attn_fused<1><<<BH_, 256, AF_SMEM(1)>>>();

    // #6: output projection
    gemm16<<<dim3(C_/128, M_TOT/128, 1), 128, G16_SMEM>>>(out, 0);
}